// round 2
// baseline (speedup 1.0000x reference)
#include <cuda_runtime.h>

typedef unsigned long long u64;

#define VJ   42
#define NTH  512

// ---- shared memory layout (float offsets) ----
#define OFF_ADJ  0        // 3528  : adj1 (1764) + adj2 (1764)
#define OFF_W2   3528     // 8448  : W2 chunk [256][33] (pad-33)
#define OFF_W1   11976    // 8256  : W1t [64][129]
#define OFF_W0   20232    // 4160  : W0t [64][65]
#define OFF_BUFA 24392    // 5376f : u64[2688]  x / agg1-out (42x64 f32x2)
#define OFF_BUFB 29768    // 5376f : u64[2688]  h1
#define OFF_BUFC 35144    // 10752f: u64[5376]  h2 (42x128) / lin2 partials [16][256]
#define OFF_BUFD 45896    // 10752f: u64[5376]  agg2-out (42x128)
#define SMEM_FLOATS 56648
#define SMEM_BYTES  (SMEM_FLOATS * 4)   // 226592 B <= 232448 opt-in max

__device__ float g_adj[2 * VJ * VJ];

__device__ __forceinline__ u64 pk2(float x, float y) {
    u64 r; asm("mov.b64 %0,{%1,%2};" : "=l"(r) : "f"(x), "f"(y)); return r;
}
__device__ __forceinline__ u64 dup2(float x) {
    u64 r; asm("mov.b64 %0,{%1,%1};" : "=l"(r) : "f"(x)); return r;
}
__device__ __forceinline__ void upk2(u64 v, float& x, float& y) {
    asm("mov.b64 {%0,%1},%2;" : "=f"(x), "=f"(y) : "l"(v));
}
__device__ __forceinline__ u64 f2fma(u64 a, u64 b, u64 c) {
    u64 d; asm("fma.rn.f32x2 %0,%1,%2,%3;" : "=l"(d) : "l"(a), "l"(b), "l"(c)); return d;
}
__device__ __forceinline__ u64 bnrelu2(u64 v, float sc, float sh) {
    float x, y; upk2(v, x, y);
    x = fmaxf(fmaf(x, sc, sh), 0.f);
    y = fmaxf(fmaf(y, sc, sh), 0.f);
    return pk2(x, y);
}

// ---------------- adjacency prep ----------------
__constant__ int c_ei[23] = {0,1,2,3,0,5,6,7,0,9,10,11,0,13,14,15,0,17,18,19,5,9,13};
__constant__ int c_ej[23] = {1,2,3,4,5,6,7,8,9,10,11,12,13,14,15,16,17,18,19,20,9,13,17};

__global__ void agcn_prep(const float* __restrict__ B1, const float* __restrict__ B2) {
    __shared__ float base[VJ][VJ];
    __shared__ float rs[VJ];
    int t = threadIdx.x;
    for (int e = t; e < VJ * VJ; e += blockDim.x) ((float*)base)[e] = 0.f;
    __syncthreads();
    if (t < 23) {
        int i = c_ei[t], j = c_ej[t];
        base[i][j] = 1.f; base[j][i] = 1.f;
        base[21 + i][21 + j] = 1.f; base[21 + j][21 + i] = 1.f;
    }
    if (t == 31) { base[0][21] = 1.f; base[21][0] = 1.f; }
    if (t >= 64 && t < 64 + VJ) base[t - 64][t - 64] = 1.f;
    __syncthreads();
    if (t < VJ) {
        float s = 0.f;
        for (int u = 0; u < VJ; u++) s += base[t][u];
        rs[t] = 1.f / s;
    }
    __syncthreads();
    if (t < 2 * VJ) {
        int m = t / VJ, v = t % VJ;
        const float* Bm = m ? B2 : B1;
        float row[VJ];
        float mx = -1e30f;
        for (int u = 0; u < VJ; u++) {
            float val = base[v][u] * rs[v] + Bm[v * VJ + u];
            row[u] = val;
            mx = fmaxf(mx, val);
        }
        float se = 0.f;
        for (int u = 0; u < VJ; u++) { row[u] = expf(row[u] - mx); se += row[u]; }
        float inv = 1.f / se;
        for (int u = 0; u < VJ; u++) g_adj[m * VJ * VJ + v * VJ + u] = row[u] * inv;
    }
}

// ---------------- lin2 helpers (templated so all reg-array indexing is constant) ----------------
template <int NK>
__device__ __forceinline__ void l2_init(u64 (&acc)[3][8], const float* __restrict__ b2,
                                        int lane, int kb) {
#pragma unroll
    for (int k = 0; k < NK; k++) {
        u64 bv = dup2(__ldg(b2 + lane + 32 * (kb + k)));
#pragma unroll
        for (int j = 0; j < 3; j++) acc[j][k] = bv;
    }
}

template <int NK>
__device__ __forceinline__ void l2_comp(u64 (&acc)[3][8], const u64* __restrict__ D,
                                        const float* __restrict__ w2c,
                                        int jb, int kb, int lane, int f0) {
#pragma unroll 4
    for (int f = 0; f < 32; f++) {
        u64 a0 = D[(jb + 0) * 128 + f0 + f];
        u64 a1 = D[(jb + 1) * 128 + f0 + f];
        u64 a2 = D[(jb + 2) * 128 + f0 + f];
#pragma unroll
        for (int k = 0; k < NK; k++) {
            u64 w = dup2(w2c[(lane + 32 * (kb + k)) * 33 + f]);
            acc[0][k] = f2fma(a0, w, acc[0][k]);
            acc[1][k] = f2fma(a1, w, acc[1][k]);
            acc[2][k] = f2fma(a2, w, acc[2][k]);
        }
    }
}

template <int NK>
__device__ __forceinline__ void l2_epi(u64 (&acc)[3][8], u64* __restrict__ P,
                                       const float* __restrict__ g2, const float* __restrict__ be2,
                                       int warp, int lane, int jb, int kb, float RS) {
#pragma unroll
    for (int k = 0; k < NK; k++) {
        int d = lane + 32 * (kb + k);
        float sx = 0.f, sy = 0.f;
#pragma unroll
        for (int j = 0; j < 3; j++) {
            int v = jb + j;
            float sc = __ldg(g2 + v) * RS;
            float sh = __ldg(be2 + v);
            float tx, ty; upk2(acc[j][k], tx, ty);
            sx += fmaxf(fmaf(tx, sc, sh), 0.f);
            sy += fmaxf(fmaf(ty, sc, sh), 0.f);
        }
        P[warp * 256 + d] = pk2(sx, sy);
    }
}

// ---------------- fused main kernel: 2 samples per CTA, packed in f32x2 lanes ----------------
__global__ __launch_bounds__(NTH, 1) void agcn_main(
    const float* __restrict__ x,
    const float* __restrict__ W0, const float* __restrict__ b0,
    const float* __restrict__ g0, const float* __restrict__ be0,
    const float* __restrict__ W1, const float* __restrict__ b1,
    const float* __restrict__ g1, const float* __restrict__ be1,
    const float* __restrict__ W2, const float* __restrict__ b2,
    const float* __restrict__ g2, const float* __restrict__ be2,
    const float* __restrict__ Wc, const float* __restrict__ bc,
    float* __restrict__ out)
{
    extern __shared__ float sm[];
    float* s_adj = sm + OFF_ADJ;
    float* s_w2  = sm + OFF_W2;
    float* s_w1  = sm + OFF_W1;
    float* s_w0  = sm + OFF_W0;
    u64* bufA = (u64*)(sm + OFF_BUFA);
    u64* bufB = (u64*)(sm + OFF_BUFB);
    u64* bufC = (u64*)(sm + OFF_BUFC);
    u64* bufD = (u64*)(sm + OFF_BUFD);

    const int tid  = threadIdx.x;
    const int lane = tid & 31;
    const int warp = tid >> 5;
    const int n0   = blockIdx.x * 2;
    const float RS = rsqrtf(1.00001f);

    // ---- stage 0: load x (2 rows, packed), W0t, W1t, adj ----
    {
        const float* x0 = x + (size_t)n0 * 2688;
        const float* x1 = x0 + 2688;
        for (int e = tid; e < 2688; e += NTH) bufA[e] = pk2(x0[e], x1[e]);
        for (int e = tid; e < 4096; e += NTH) {          // W0t[f][c] = W0[c][f], pad 65
            int c = e >> 6, f = e & 63;
            s_w0[f * 65 + c] = W0[e];
        }
        for (int e = tid; e < 8192; e += NTH) {          // W1t[f][d] = W1[d][f], pad 129
            int d = e >> 6, f = e & 63;
            s_w1[f * 129 + d] = W1[e];
        }
        for (int e = tid; e < 2 * VJ * VJ; e += NTH) s_adj[e] = g_adj[e];
    }
    __syncthreads();

    // ---- stage 1: proj 64->64, BN+ReLU.  warps 0..6 x 6 joints; others prefetch W2 chunk0 ----
    if (warp < 7) {
        const int jb = warp * 6;
        u64 acc0[6], acc1[6];
        {
            u64 bb0 = dup2(__ldg(b0 + lane));
            u64 bb1 = dup2(__ldg(b0 + lane + 32));
#pragma unroll
            for (int j = 0; j < 6; j++) { acc0[j] = bb0; acc1[j] = bb1; }
        }
#pragma unroll 4
        for (int f = 0; f < 64; f++) {
            u64 w0 = dup2(s_w0[f * 65 + lane]);
            u64 w1 = dup2(s_w0[f * 65 + lane + 32]);
#pragma unroll
            for (int j = 0; j < 6; j++) {
                u64 a = bufA[(jb + j) * 64 + f];
                acc0[j] = f2fma(a, w0, acc0[j]);
                acc1[j] = f2fma(a, w1, acc1[j]);
            }
        }
#pragma unroll
        for (int j = 0; j < 6; j++) {
            int v = jb + j;
            float sc = __ldg(g0 + v) * RS, sh = __ldg(be0 + v);
            bufB[v * 64 + lane]      = bnrelu2(acc0[j], sc, sh);
            bufB[v * 64 + lane + 32] = bnrelu2(acc1[j], sc, sh);
        }
    } else {
        // prefetch W2 chunk 0 into s_w2 (pad-33 layout)
        for (int e = tid - 224; e < 8192; e += NTH - 224) {
            int c = e >> 5, f = e & 31;
            s_w2[c * 33 + f] = W2[c * 128 + f];
        }
    }
    __syncthreads();

    // ---- stage 2: agg1 (adj1 @ h1) -> bufA ----
    if (warp < 7) {
        const int jb = warp * 6;
        const float* adj1 = s_adj;
        u64 acc0[6], acc1[6];
#pragma unroll
        for (int j = 0; j < 6; j++) { acc0[j] = 0ull; acc1[j] = 0ull; }
        for (int u = 0; u < VJ; u++) {
            u64 h0 = bufB[u * 64 + lane];
            u64 h1 = bufB[u * 64 + lane + 32];
#pragma unroll
            for (int j = 0; j < 6; j++) {
                u64 w = dup2(adj1[(jb + j) * VJ + u]);
                acc0[j] = f2fma(h0, w, acc0[j]);
                acc1[j] = f2fma(h1, w, acc1[j]);
            }
        }
#pragma unroll
        for (int j = 0; j < 6; j++) {
            bufA[(jb + j) * 64 + lane]      = acc0[j];
            bufA[(jb + j) * 64 + lane + 32] = acc1[j];
        }
    }
    __syncthreads();

    // ---- stage 3: lin1 64->128, BN+ReLU -> bufC ----
    if (warp < 7) {
        const int jb = warp * 6;
        u64 acc[6][4];
#pragma unroll
        for (int k = 0; k < 4; k++) {
            u64 bv = dup2(__ldg(b1 + lane + 32 * k));
#pragma unroll
            for (int j = 0; j < 6; j++) acc[j][k] = bv;
        }
#pragma unroll 2
        for (int f = 0; f < 64; f++) {
            u64 w[4];
#pragma unroll
            for (int k = 0; k < 4; k++) w[k] = dup2(s_w1[f * 129 + lane + 32 * k]);
#pragma unroll
            for (int j = 0; j < 6; j++) {
                u64 a = bufA[(jb + j) * 64 + f];
#pragma unroll
                for (int k = 0; k < 4; k++) acc[j][k] = f2fma(a, w[k], acc[j][k]);
            }
        }
#pragma unroll
        for (int j = 0; j < 6; j++) {
            int v = jb + j;
            float sc = __ldg(g1 + v) * RS, sh = __ldg(be1 + v);
#pragma unroll
            for (int k = 0; k < 4; k++)
                bufC[v * 128 + lane + 32 * k] = bnrelu2(acc[j][k], sc, sh);
        }
    }
    __syncthreads();

    // ---- stage 4: agg2 (adj2 @ h2) -> bufD ----
    if (warp < 7) {
        const int jb = warp * 6;
        const float* adj2 = s_adj + VJ * VJ;
        u64 acc[6][4];
#pragma unroll
        for (int j = 0; j < 6; j++)
#pragma unroll
            for (int k = 0; k < 4; k++) acc[j][k] = 0ull;
        for (int u = 0; u < VJ; u++) {
            u64 h[4];
#pragma unroll
            for (int k = 0; k < 4; k++) h[k] = bufC[u * 128 + lane + 32 * k];
#pragma unroll
            for (int j = 0; j < 6; j++) {
                u64 w = dup2(adj2[(jb + j) * VJ + u]);
#pragma unroll
                for (int k = 0; k < 4; k++) acc[j][k] = f2fma(h[k], w, acc[j][k]);
            }
        }
#pragma unroll
        for (int j = 0; j < 6; j++)
#pragma unroll
            for (int k = 0; k < 4; k++)
                bufD[(jb + j) * 128 + lane + 32 * k] = acc[j][k];
    }
    __syncthreads();

    // ---- stage 5: lin2 128->256 + BN + ReLU + joint-mean partials ----
    // warps 0..11: 3 joints x 8 channel-groups; warps 12..15: 3 joints x 4 groups (tail split)
    {
        const bool full = (warp < 12);
        int jb, kb;
        if (full) { jb = warp * 3; kb = 0; }
        else      { jb = 36 + ((warp - 12) >> 1) * 3; kb = ((warp - 12) & 1) * 4; }

        u64 acc[3][8];
        if (full) l2_init<8>(acc, b2, lane, 0);
        else      l2_init<4>(acc, b2, lane, kb);

        for (int fc = 0; fc < 4; fc++) {
            if (fc > 0) {
                __syncthreads();
                for (int e = tid; e < 8192; e += NTH) {
                    int c = e >> 5, f = e & 31;
                    s_w2[c * 33 + f] = W2[c * 128 + fc * 32 + f];
                }
            }
            __syncthreads();
            if (full) l2_comp<8>(acc, bufD, s_w2, jb, 0, lane, fc * 32);
            else      l2_comp<4>(acc, bufD, s_w2, jb, kb, lane, fc * 32);
        }

        // partials go into bufC (free now) as P[warp][256]
        u64* P = bufC;
        if (full) l2_epi<8>(acc, P, g2, be2, warp, lane, jb, 0, RS);
        else {
            l2_epi<4>(acc, P, g2, be2, warp, lane, jb, kb, RS);
            int ko = (kb == 0) ? 4 : 0;   // zero the unowned half
#pragma unroll
            for (int k = 0; k < 4; k++) P[warp * 256 + lane + 32 * (ko + k)] = 0ull;
        }
    }
    __syncthreads();

    // ---- stage 6: reduce partials -> feat (x 1/42) in bufA ----
    if (tid < 256) {
        float sx = 0.f, sy = 0.f;
        const u64* P = bufC;
#pragma unroll
        for (int w = 0; w < 16; w++) {
            float tx, ty; upk2(P[w * 256 + tid], tx, ty);
            sx += tx; sy += ty;
        }
        const float inv = 1.0f / 42.0f;
        bufA[tid] = pk2(sx * inv, sy * inv);
    }
    __syncthreads();

    // ---- stage 7: classifier (2 classes, one warp each) ----
    if (warp < 2) {
        const int k = warp;
        const float* Wck = Wc + k * 256;
        float ax = 0.f, ay = 0.f;
#pragma unroll
        for (int i = 0; i < 8; i++) {
            int d = lane + 32 * i;
            float tx, ty; upk2(bufA[d], tx, ty);
            float w = __ldg(Wck + d);
            ax = fmaf(tx, w, ax);
            ay = fmaf(ty, w, ay);
        }
#pragma unroll
        for (int o = 16; o; o >>= 1) {
            ax += __shfl_xor_sync(0xffffffffu, ax, o);
            ay += __shfl_xor_sync(0xffffffffu, ay, o);
        }
        if (lane == 0) {
            float bk = __ldg(bc + k);
            out[(size_t)n0 * 2 + k]       = ax + bk;
            out[(size_t)(n0 + 1) * 2 + k] = ay + bk;
        }
    }
}

extern "C" void kernel_launch(void* const* d_in, const int* in_sizes, int n_in,
                              void* d_out, int out_size) {
    const float* x   = (const float*)d_in[0];
    const float* W0  = (const float*)d_in[1];
    const float* b0  = (const float*)d_in[2];
    const float* g0  = (const float*)d_in[3];
    const float* be0 = (const float*)d_in[4];
    const float* W1  = (const float*)d_in[5];
    const float* b1  = (const float*)d_in[6];
    const float* B1  = (const float*)d_in[7];
    const float* g1  = (const float*)d_in[8];
    const float* be1 = (const float*)d_in[9];
    const float* W2  = (const float*)d_in[10];
    const float* b2  = (const float*)d_in[11];
    const float* B2  = (const float*)d_in[12];
    const float* g2  = (const float*)d_in[13];
    const float* be2 = (const float*)d_in[14];
    const float* Wc  = (const float*)d_in[15];
    const float* bc  = (const float*)d_in[16];
    float* out = (float*)d_out;

    int N = in_sizes[0] / (VJ * 64);

    cudaFuncSetAttribute(agcn_main, cudaFuncAttributeMaxDynamicSharedMemorySize, SMEM_BYTES);

    agcn_prep<<<1, 128>>>(B1, B2);
    agcn_main<<<N / 2, NTH, SMEM_BYTES>>>(x, W0, b0, g0, be0, W1, b1, g1, be1,
                                          W2, b2, g2, be2, Wc, bc, out);
}